// round 6
// baseline (speedup 1.0000x reference)
#include <cuda_runtime.h>
#include <cstdint>

#define ROWS        8192
#define COLS        32768
#define K_TOP       32
#define PRE_THRESH  2.8f

#define SEGS_PER_ROW 4
#define SEG          (COLS / SEGS_PER_ROW)
#define STH          512
#define SEG_ITERS    (SEG / 4 / STH)      // 4
#define SEG_CAP      128                   // per-segment cap (mean ~21)
#define CAND_CAP     256                   // per-row cap (mean ~84, sigma ~9.1)

#define QTH          512
#define ROWS_PER_BLK (QTH / 32)            // 16 (one warp per row)

// Global scratch (zero-init at load; select kernel resets counters)
__device__ unsigned long long g_cand[(size_t)ROWS * CAND_CAP];
__device__ int                g_cnt[ROWS];

__device__ __forceinline__ unsigned fmap(float f) {
    unsigned b = __float_as_uint(f);
    return (b & 0x80000000u) ? ~b : (b | 0x80000000u);
}
__device__ __forceinline__ float unfmap(unsigned u) {
    unsigned b = (u & 0x80000000u) ? (u ^ 0x80000000u) : ~u;
    return __uint_as_float(b);
}
// unique key: value desc, index asc tiebreak (matches jax.lax.top_k)
__device__ __forceinline__ unsigned long long make_key(float v, int idx) {
    return ((unsigned long long)fmap(v) << 32) | (unsigned)(~idx);
}

// ---------------------------------------------------------------------------
// Kernel 1: pure streaming pass. Front-batched loads (MLP=4), zero-fill,
// rare candidate gather at the 2.8-sigma threshold.
// ---------------------------------------------------------------------------
__global__ __launch_bounds__(STH) void stream_kernel(
    const float* __restrict__ x, float* __restrict__ out)
{
    __shared__ int s_cnt;
    __shared__ int s_base;
    __shared__ unsigned long long s_cand[SEG_CAP];

    const int seg_id = blockIdx.x;
    const int row = seg_id >> 2;
    const int seg = seg_id & 3;
    const size_t base = (size_t)row * COLS + (size_t)seg * SEG;
    const int tid = threadIdx.x;

    if (tid == 0) s_cnt = 0;
    __syncthreads();

    const float4* __restrict__ xin = reinterpret_cast<const float4*>(x + base);
    float4* __restrict__       zo  = reinterpret_cast<float4*>(out + base);
    const float4 z4 = make_float4(0.f, 0.f, 0.f, 0.f);

    float4 v[SEG_ITERS];
    #pragma unroll
    for (int k = 0; k < SEG_ITERS; k++)
        v[k] = __ldcs(&xin[tid + k * STH]);
    #pragma unroll
    for (int k = 0; k < SEG_ITERS; k++)
        __stcs(&zo[tid + k * STH], z4);

    #pragma unroll
    for (int k = 0; k < SEG_ITERS; k++) {
        const int gidx = seg * SEG + (tid + k * STH) * 4;
        if (v[k].x >= PRE_THRESH) { int p = atomicAdd(&s_cnt, 1); if (p < SEG_CAP) s_cand[p] = make_key(v[k].x, gidx + 0); }
        if (v[k].y >= PRE_THRESH) { int p = atomicAdd(&s_cnt, 1); if (p < SEG_CAP) s_cand[p] = make_key(v[k].y, gidx + 1); }
        if (v[k].z >= PRE_THRESH) { int p = atomicAdd(&s_cnt, 1); if (p < SEG_CAP) s_cand[p] = make_key(v[k].z, gidx + 2); }
        if (v[k].w >= PRE_THRESH) { int p = atomicAdd(&s_cnt, 1); if (p < SEG_CAP) s_cand[p] = make_key(v[k].w, gidx + 3); }
    }
    __syncthreads();

    const int cnt = s_cnt;
    if (tid == 0) {
        // poison the row count on segment overflow -> select falls back
        int add = (cnt > SEG_CAP) ? (CAND_CAP + 1 + cnt) : cnt;
        s_base = atomicAdd(&g_cnt[row], add);
    }
    __syncthreads();

    const int wcnt = min(cnt, SEG_CAP);
    const int b = s_base;
    for (int j = tid; j < wcnt; j += STH) {
        const int pos = b + j;
        if (pos < CAND_CAP)
            g_cand[(size_t)row * CAND_CAP + pos] = s_cand[j];
    }
}

// ---------------------------------------------------------------------------
// Kernel 2: warp-per-row exact top-K. Fast path: O(c^2) rank-select over
// unique 64-bit keys (lockstep broadcast LDS). Fallback: warp-level full-row
// radix select (never taken for this data; exact for arbitrary input).
// ---------------------------------------------------------------------------
__global__ __launch_bounds__(QTH) void select_kernel(
    const float* __restrict__ x, float* __restrict__ out)
{
    // per-warp buffer: keys (fast path) or 256-bin histogram (fallback)
    __shared__ unsigned long long s_buf[ROWS_PER_BLK][CAND_CAP];

    const int warp = threadIdx.x >> 5;
    const int lane = threadIdx.x & 31;
    const int row  = blockIdx.x * ROWS_PER_BLK + warp;
    const size_t row_off = (size_t)row * COLS;

    unsigned long long* const keys = s_buf[warp];

    const int cnt = g_cnt[row];
    const bool fast = (cnt >= K_TOP) && (cnt <= CAND_CAP);

    if (fast) {
        // load candidates (coalesced within warp)
        for (int j = lane; j < cnt; j += 32)
            keys[j] = g_cand[(size_t)row * CAND_CAP + j];
        __syncwarp();

        // each lane owns keys lane, lane+32, ... (<=8); rank via broadcast loop
        unsigned long long mine[CAND_CAP / 32];
        int nmine = 0;
        for (int j = lane; j < cnt; j += 32)
            mine[nmine++] = keys[j];

        int rank[CAND_CAP / 32];
        #pragma unroll
        for (int q = 0; q < CAND_CAP / 32; q++) rank[q] = 0;

        for (int j = 0; j < cnt; j++) {
            const unsigned long long kj = keys[j];   // broadcast read
            #pragma unroll
            for (int q = 0; q < CAND_CAP / 32; q++)
                if (q < nmine) rank[q] += (kj > mine[q]);
        }
        #pragma unroll
        for (int q = 0; q < CAND_CAP / 32; q++) {
            if (q < nmine && rank[q] < K_TOP) {
                const int idx = (int)(~(unsigned)mine[q]) & (COLS - 1);
                const float v = unfmap((unsigned)(mine[q] >> 32));
                out[row_off + idx] = fmaxf(v, 0.f);
            }
        }
    } else {
        // ---------- warp-level full-row radix select (correctness path) ----
        int* const hist = (int*)keys;   // reuse buffer: 256 bins
        unsigned long long prefix = 0, T = 0;
        int want = K_TOP;

        for (int shift = 56; shift >= 0; shift -= 8) {
            for (int d = lane; d < 256; d += 32) hist[d] = 0;
            __syncwarp();
            for (int j = lane; j < COLS; j += 32) {
                unsigned long long key = make_key(x[row_off + j], j);
                if (shift == 56 || (key >> (shift + 8)) == prefix)
                    atomicAdd(&hist[(int)((key >> shift) & 255)], 1);
            }
            __syncwarp();
            int digit = 0, nwant = 0, c = 0;
            if (lane == 0) {
                int acc = 0, d = 255;
                for (; d >= 0; d--) {
                    if (acc + hist[d] >= want) break;
                    acc += hist[d];
                }
                if (d < 0) d = 0;
                digit = d; nwant = want - acc; c = hist[d];
            }
            digit = __shfl_sync(0xffffffffu, digit, 0);
            nwant = __shfl_sync(0xffffffffu, nwant, 0);
            c     = __shfl_sync(0xffffffffu, c, 0);
            __syncwarp();

            prefix = (prefix << 8) | (unsigned long long)digit;
            want = nwant;
            if (want == c) { T = prefix << shift; break; }
            // keys unique -> by shift==0 the bin size is 1 and want==c==1,
            // so this loop always exits via the break above.
        }
        for (int j = lane; j < COLS; j += 32) {
            unsigned long long key = make_key(x[row_off + j], j);
            if (key >= T) {
                const int idx = (int)(~(unsigned)key) & (COLS - 1);
                const float v = unfmap((unsigned)(key >> 32));
                out[row_off + idx] = fmaxf(v, 0.f);
            }
        }
    }

    // Reset counter for deterministic graph replays.
    __syncwarp();
    if (lane == 0) g_cnt[row] = 0;
}

extern "C" void kernel_launch(void* const* d_in, const int* in_sizes, int n_in,
                              void* d_out, int out_size)
{
    const float* x = (const float*)d_in[0];
    float* out = (float*)d_out;
    stream_kernel<<<ROWS * SEGS_PER_ROW, STH>>>(x, out);
    select_kernel<<<ROWS / ROWS_PER_BLK, QTH>>>(x, out);
}

// round 8
// speedup vs baseline: 1.0454x; 1.0454x over previous
#include <cuda_runtime.h>
#include <cstdint>

#define ROWS        8192
#define COLS        32768
#define K_TOP       32
#define PRE_THRESH  2.8f

#define SEGS_PER_ROW 4
#define SEG          (COLS / SEGS_PER_ROW)
#define STH          512
#define SEG_ITERS    (SEG / 4 / STH)      // 4
#define SEG_CAP      128                   // per-segment cap (mean ~21)
#define CAND_CAP     256                   // per-row cap (mean ~84, sigma ~9.1)
#define QTH          128                   // select threads (1 row/block)

// Global scratch (zero-init at load; select kernel resets counters)
__device__ unsigned long long g_cand[(size_t)ROWS * CAND_CAP];
__device__ int                g_cnt[ROWS];

__device__ __forceinline__ unsigned fmap(float f) {
    unsigned b = __float_as_uint(f);
    return (b & 0x80000000u) ? ~b : (b | 0x80000000u);
}
__device__ __forceinline__ float unfmap(unsigned u) {
    unsigned b = (u & 0x80000000u) ? (u ^ 0x80000000u) : ~u;
    return __uint_as_float(b);
}
// unique key: value desc, index asc tiebreak (matches jax.lax.top_k)
__device__ __forceinline__ unsigned long long make_key(float v, int idx) {
    return ((unsigned long long)fmap(v) << 32) | (unsigned)(~idx);
}

// ---------------------------------------------------------------------------
// Kernel 1: pure streaming pass (unchanged from R5 — ~87% of HBM spec).
// ---------------------------------------------------------------------------
__global__ __launch_bounds__(STH) void stream_kernel(
    const float* __restrict__ x, float* __restrict__ out)
{
    __shared__ int s_cnt;
    __shared__ int s_base;
    __shared__ unsigned long long s_cand[SEG_CAP];

    const int seg_id = blockIdx.x;
    const int row = seg_id >> 2;
    const int seg = seg_id & 3;
    const size_t base = (size_t)row * COLS + (size_t)seg * SEG;
    const int tid = threadIdx.x;

    if (tid == 0) s_cnt = 0;
    __syncthreads();

    const float4* __restrict__ xin = reinterpret_cast<const float4*>(x + base);
    float4* __restrict__       zo  = reinterpret_cast<float4*>(out + base);
    const float4 z4 = make_float4(0.f, 0.f, 0.f, 0.f);

    float4 v[SEG_ITERS];
    #pragma unroll
    for (int k = 0; k < SEG_ITERS; k++)
        v[k] = __ldcs(&xin[tid + k * STH]);
    #pragma unroll
    for (int k = 0; k < SEG_ITERS; k++)
        __stcs(&zo[tid + k * STH], z4);

    #pragma unroll
    for (int k = 0; k < SEG_ITERS; k++) {
        const int gidx = seg * SEG + (tid + k * STH) * 4;
        if (v[k].x >= PRE_THRESH) { int p = atomicAdd(&s_cnt, 1); if (p < SEG_CAP) s_cand[p] = make_key(v[k].x, gidx + 0); }
        if (v[k].y >= PRE_THRESH) { int p = atomicAdd(&s_cnt, 1); if (p < SEG_CAP) s_cand[p] = make_key(v[k].y, gidx + 1); }
        if (v[k].z >= PRE_THRESH) { int p = atomicAdd(&s_cnt, 1); if (p < SEG_CAP) s_cand[p] = make_key(v[k].z, gidx + 2); }
        if (v[k].w >= PRE_THRESH) { int p = atomicAdd(&s_cnt, 1); if (p < SEG_CAP) s_cand[p] = make_key(v[k].w, gidx + 3); }
    }
    __syncthreads();

    const int cnt = s_cnt;
    if (tid == 0) {
        // poison the row count on segment overflow -> select falls back
        int add = (cnt > SEG_CAP) ? (CAND_CAP + 1 + cnt) : cnt;
        s_base = atomicAdd(&g_cnt[row], add);
    }
    __syncthreads();

    const int wcnt = min(cnt, SEG_CAP);
    const int b = s_base;
    for (int j = tid; j < wcnt; j += STH) {
        const int pos = b + j;
        if (pos < CAND_CAP)
            g_cand[(size_t)row * CAND_CAP + pos] = s_cand[j];
    }
}

// ---------------------------------------------------------------------------
// Kernel 2: 1 row/block, 128 threads, thread-per-candidate rank-select.
// Candidate loads issued unconditionally (no dependency on cnt); stale slots
// masked out of the rank loop. Fallback: warp-0 radix (exact, never taken).
// ---------------------------------------------------------------------------
__global__ __launch_bounds__(QTH) void select_kernel(
    const float* __restrict__ x, float* __restrict__ out)
{
    __shared__ unsigned long long s_keys[CAND_CAP];
    __shared__ unsigned long long s_T;

    const int row = blockIdx.x;
    const size_t row_off = (size_t)row * COLS;
    const int tid = threadIdx.x;

    // All three loads independent -> issued back-to-back, latencies overlap.
    const size_t cb = (size_t)row * CAND_CAP;
    const unsigned long long k0 = g_cand[cb + tid];
    const unsigned long long k1 = g_cand[cb + tid + QTH];
    const int cnt = g_cnt[row];

    s_keys[tid]       = k0;
    s_keys[tid + QTH] = k1;
    __syncthreads();

    const bool fast = (cnt >= K_TOP) && (cnt <= CAND_CAP);

    if (fast) {
        int r0 = 0, r1 = 0;
        for (int j = 0; j < cnt; j++) {
            const unsigned long long kj = s_keys[j];   // broadcast LDS
            r0 += (kj > k0);
            r1 += (kj > k1);
        }
        if (tid < cnt && r0 < K_TOP) {
            const int idx = (int)(~(unsigned)k0) & (COLS - 1);
            out[row_off + idx] = fmaxf(unfmap((unsigned)(k0 >> 32)), 0.f);
        }
        if (tid + QTH < cnt && r1 < K_TOP) {
            const int idx = (int)(~(unsigned)k1) & (COLS - 1);
            out[row_off + idx] = fmaxf(unfmap((unsigned)(k1 >> 32)), 0.f);
        }
    } else {
        // -------- fallback: warp-0 full-row radix select (exact) ----------
        int* const hist = (int*)s_keys;   // reuse: 256 bins (1 KB of 2 KB)
        const int lane = tid & 31;
        if (tid < 32) {
            unsigned long long prefix = 0, T = 0;
            int want = K_TOP;
            for (int shift = 56; shift >= 0; shift -= 8) {
                for (int d = lane; d < 256; d += 32) hist[d] = 0;
                __syncwarp();
                for (int j = lane; j < COLS; j += 32) {
                    unsigned long long key = make_key(x[row_off + j], j);
                    if (shift == 56 || (key >> (shift + 8)) == prefix)
                        atomicAdd(&hist[(int)((key >> shift) & 255)], 1);
                }
                __syncwarp();
                int digit = 0, nwant = 0, c = 0;
                if (lane == 0) {
                    int acc = 0, d = 255;
                    for (; d >= 0; d--) {
                        if (acc + hist[d] >= want) break;
                        acc += hist[d];
                    }
                    if (d < 0) d = 0;
                    digit = d; nwant = want - acc; c = hist[d];
                }
                digit = __shfl_sync(0xffffffffu, digit, 0);
                nwant = __shfl_sync(0xffffffffu, nwant, 0);
                c     = __shfl_sync(0xffffffffu, c, 0);
                __syncwarp();
                prefix = (prefix << 8) | (unsigned long long)digit;
                want = nwant;
                if (want == c) { T = prefix << shift; break; }
                // unique keys -> exits via break by shift==0 (bin size 1)
            }
            if (lane == 0) s_T = T;
        }
        __syncthreads();
        const unsigned long long T = s_T;
        for (int j = tid; j < COLS; j += QTH) {
            unsigned long long key = make_key(x[row_off + j], j);
            if (key >= T) {
                const int idx = (int)(~(unsigned)key) & (COLS - 1);
                out[row_off + idx] = fmaxf(unfmap((unsigned)(key >> 32)), 0.f);
            }
        }
    }

    // Reset counter for deterministic graph replays.
    __syncthreads();
    if (tid == 0) g_cnt[row] = 0;
}

extern "C" void kernel_launch(void* const* d_in, const int* in_sizes, int n_in,
                              void* d_out, int out_size)
{
    const float* x = (const float*)d_in[0];
    float* out = (float*)d_out;
    stream_kernel<<<ROWS * SEGS_PER_ROW, STH>>>(x, out);
    select_kernel<<<ROWS, QTH>>>(x, out);
}

// round 9
// speedup vs baseline: 1.0766x; 1.0299x over previous
#include <cuda_runtime.h>
#include <cstdint>

#define ROWS        8192
#define COLS        32768
#define K_TOP       32
#define PRE_THRESH  2.8f

#define SEGS_PER_ROW 4
#define SEG          (COLS / SEGS_PER_ROW)
#define STH          512
#define SEG_ITERS    (SEG / 4 / STH)      // 4
#define SEG_CAP      128                   // per-segment cap (mean ~21)
#define CAND_CAP     256                   // per-row cap (mean ~84, sigma ~9.1)
#define QTH          128                   // select threads (1 row/block)

// Global scratch (zero-init at load; select kernel resets counters)
__device__ unsigned long long g_cand[(size_t)ROWS * CAND_CAP];
__device__ int                g_cnt[ROWS];

__device__ __forceinline__ unsigned fmap(float f) {
    unsigned b = __float_as_uint(f);
    return (b & 0x80000000u) ? ~b : (b | 0x80000000u);
}
__device__ __forceinline__ float unfmap(unsigned u) {
    unsigned b = (u & 0x80000000u) ? (u ^ 0x80000000u) : ~u;
    return __uint_as_float(b);
}
// unique key: value desc, index asc tiebreak (matches jax.lax.top_k)
__device__ __forceinline__ unsigned long long make_key(float v, int idx) {
    return ((unsigned long long)fmap(v) << 32) | (unsigned)(~idx);
}

// ---------------------------------------------------------------------------
// Kernel 1: pure streaming pass (unchanged — ~87% of HBM spec).
// ---------------------------------------------------------------------------
__global__ __launch_bounds__(STH) void stream_kernel(
    const float* __restrict__ x, float* __restrict__ out)
{
    __shared__ int s_cnt;
    __shared__ int s_base;
    __shared__ unsigned long long s_cand[SEG_CAP];

    const int seg_id = blockIdx.x;
    const int row = seg_id >> 2;
    const int seg = seg_id & 3;
    const size_t base = (size_t)row * COLS + (size_t)seg * SEG;
    const int tid = threadIdx.x;

    if (tid == 0) s_cnt = 0;
    __syncthreads();

    const float4* __restrict__ xin = reinterpret_cast<const float4*>(x + base);
    float4* __restrict__       zo  = reinterpret_cast<float4*>(out + base);
    const float4 z4 = make_float4(0.f, 0.f, 0.f, 0.f);

    float4 v[SEG_ITERS];
    #pragma unroll
    for (int k = 0; k < SEG_ITERS; k++)
        v[k] = __ldcs(&xin[tid + k * STH]);
    #pragma unroll
    for (int k = 0; k < SEG_ITERS; k++)
        __stcs(&zo[tid + k * STH], z4);

    #pragma unroll
    for (int k = 0; k < SEG_ITERS; k++) {
        const int gidx = seg * SEG + (tid + k * STH) * 4;
        if (v[k].x >= PRE_THRESH) { int p = atomicAdd(&s_cnt, 1); if (p < SEG_CAP) s_cand[p] = make_key(v[k].x, gidx + 0); }
        if (v[k].y >= PRE_THRESH) { int p = atomicAdd(&s_cnt, 1); if (p < SEG_CAP) s_cand[p] = make_key(v[k].y, gidx + 1); }
        if (v[k].z >= PRE_THRESH) { int p = atomicAdd(&s_cnt, 1); if (p < SEG_CAP) s_cand[p] = make_key(v[k].z, gidx + 2); }
        if (v[k].w >= PRE_THRESH) { int p = atomicAdd(&s_cnt, 1); if (p < SEG_CAP) s_cand[p] = make_key(v[k].w, gidx + 3); }
    }
    __syncthreads();

    const int cnt = s_cnt;
    if (tid == 0) {
        // poison the row count on segment overflow -> select falls back
        int add = (cnt > SEG_CAP) ? (CAND_CAP + 1 + cnt) : cnt;
        s_base = atomicAdd(&g_cnt[row], add);
    }
    __syncthreads();

    const int wcnt = min(cnt, SEG_CAP);
    const int b = s_base;
    for (int j = tid; j < wcnt; j += STH) {
        const int pos = b + j;
        if (pos < CAND_CAP)
            g_cand[(size_t)row * CAND_CAP + pos] = s_cand[j];
    }
}

// ---------------------------------------------------------------------------
// Kernel 2: 1 row/block, 128 threads. Single-key rank-select with LDS.128
// vectorized broadcast reads; warps above cnt skip the loop entirely.
// Fallback: warp-0 full-row radix (exact, never taken for this data).
// ---------------------------------------------------------------------------
__global__ __launch_bounds__(QTH) void select_kernel(
    const float* __restrict__ x, float* __restrict__ out)
{
    __shared__ __align__(16) unsigned long long s_keys[CAND_CAP + 2];
    __shared__ unsigned long long s_T;

    const int row = blockIdx.x;
    const size_t row_off = (size_t)row * COLS;
    const int tid = threadIdx.x;

    // Independent loads -> issued back-to-back, latencies overlap.
    const size_t cb = (size_t)row * CAND_CAP;
    const unsigned long long k0 = g_cand[cb + tid];
    const unsigned long long k1 = g_cand[cb + tid + QTH];
    const int cnt = g_cnt[row];

    s_keys[tid]       = k0;
    s_keys[tid + QTH] = k1;
    if (tid == 0) {                 // zero-pad odd slot for the vector loop
        s_keys[CAND_CAP]     = 0;   // (also covers cnt==CAND_CAP case)
        s_keys[CAND_CAP + 1] = 0;
    }
    __syncthreads();
    if (tid == 0 && (cnt & 1) && cnt < CAND_CAP) s_keys[cnt] = 0;
    __syncthreads();

    const bool fast = (cnt >= K_TOP) && (cnt <= CAND_CAP);

    if (fast) {
        const ulonglong2* __restrict__ kv =
            reinterpret_cast<const ulonglong2*>(s_keys);
        const int nh = (cnt + 1) >> 1;

        if (cnt <= QTH) {
            // common path: one key per thread; warps >= cnt skip everything
            if (tid < cnt) {
                int r0 = 0;
                #pragma unroll 4
                for (int j = 0; j < nh; j++) {
                    const ulonglong2 p = kv[j];     // LDS.128 broadcast
                    r0 += (int)(p.x > k0) + (int)(p.y > k0);
                }
                if (r0 < K_TOP) {
                    const int idx = (int)(~(unsigned)k0) & (COLS - 1);
                    out[row_off + idx] = fmaxf(unfmap((unsigned)(k0 >> 32)), 0.f);
                }
            }
        } else {
            // rare path: cnt in (128, 256]
            int r0 = 0, r1 = 0;
            #pragma unroll 2
            for (int j = 0; j < nh; j++) {
                const ulonglong2 p = kv[j];
                r0 += (int)(p.x > k0) + (int)(p.y > k0);
                r1 += (int)(p.x > k1) + (int)(p.y > k1);
            }
            if (tid < cnt && r0 < K_TOP) {
                const int idx = (int)(~(unsigned)k0) & (COLS - 1);
                out[row_off + idx] = fmaxf(unfmap((unsigned)(k0 >> 32)), 0.f);
            }
            if (tid + QTH < cnt && r1 < K_TOP) {
                const int idx = (int)(~(unsigned)k1) & (COLS - 1);
                out[row_off + idx] = fmaxf(unfmap((unsigned)(k1 >> 32)), 0.f);
            }
        }
    } else {
        // -------- fallback: warp-0 full-row radix select (exact) ----------
        int* const hist = (int*)s_keys;   // reuse: 256 bins
        const int lane = tid & 31;
        if (tid < 32) {
            unsigned long long prefix = 0, T = 0;
            int want = K_TOP;
            for (int shift = 56; shift >= 0; shift -= 8) {
                for (int d = lane; d < 256; d += 32) hist[d] = 0;
                __syncwarp();
                for (int j = lane; j < COLS; j += 32) {
                    unsigned long long key = make_key(x[row_off + j], j);
                    if (shift == 56 || (key >> (shift + 8)) == prefix)
                        atomicAdd(&hist[(int)((key >> shift) & 255)], 1);
                }
                __syncwarp();
                int digit = 0, nwant = 0, c = 0;
                if (lane == 0) {
                    int acc = 0, d = 255;
                    for (; d >= 0; d--) {
                        if (acc + hist[d] >= want) break;
                        acc += hist[d];
                    }
                    if (d < 0) d = 0;
                    digit = d; nwant = want - acc; c = hist[d];
                }
                digit = __shfl_sync(0xffffffffu, digit, 0);
                nwant = __shfl_sync(0xffffffffu, nwant, 0);
                c     = __shfl_sync(0xffffffffu, c, 0);
                __syncwarp();
                prefix = (prefix << 8) | (unsigned long long)digit;
                want = nwant;
                if (want == c) { T = prefix << shift; break; }
                // unique keys -> exits via break by shift==0 (bin size 1)
            }
            if (lane == 0) s_T = T;
        }
        __syncthreads();
        const unsigned long long T = s_T;
        for (int j = tid; j < COLS; j += QTH) {
            unsigned long long key = make_key(x[row_off + j], j);
            if (key >= T) {
                const int idx = (int)(~(unsigned)key) & (COLS - 1);
                out[row_off + idx] = fmaxf(unfmap((unsigned)(key >> 32)), 0.f);
            }
        }
    }

    // Reset counter for deterministic graph replays.
    __syncthreads();
    if (tid == 0) g_cnt[row] = 0;
}

extern "C" void kernel_launch(void* const* d_in, const int* in_sizes, int n_in,
                              void* d_out, int out_size)
{
    const float* x = (const float*)d_in[0];
    float* out = (float*)d_out;
    stream_kernel<<<ROWS * SEGS_PER_ROW, STH>>>(x, out);
    select_kernel<<<ROWS, QTH>>>(x, out);
}

// round 11
// speedup vs baseline: 1.0917x; 1.0139x over previous
#include <cuda_runtime.h>
#include <cstdint>

#define ROWS        8192
#define COLS        32768
#define K_TOP       32
#define PRE_THRESH  2.8f

#define NTH         512
#define ITERS       (COLS / 4 / NTH)       // 16 float4 per thread
#define BATCH       4                       // front-batched loads per group
#define GROUPS      (ITERS / BATCH)         // 4
#define CAND_CAP    192                     // mean ~84, sigma ~9.1 -> 11.8 sigma

__device__ __forceinline__ unsigned fmap(float f) {
    unsigned b = __float_as_uint(f);
    return (b & 0x80000000u) ? ~b : (b | 0x80000000u);
}
__device__ __forceinline__ float unfmap(unsigned u) {
    unsigned b = (u & 0x80000000u) ? (u ^ 0x80000000u) : ~u;
    return __uint_as_float(b);
}
// unique key: value desc, index asc tiebreak (matches jax.lax.top_k)
__device__ __forceinline__ unsigned long long make_key(float v, int idx) {
    return ((unsigned long long)fmap(v) << 32) | (unsigned)(~idx);
}

// warp-aggregated histogram add (fallback path only)
__device__ __forceinline__ void hist_add(int* hist, int digit) {
    const unsigned act   = __activemask();
    const unsigned peers = __match_any_sync(act, digit);
    const int      lane  = threadIdx.x & 31;
    if ((__ffs(peers) - 1) == lane)
        atomicAdd(&hist[digit], __popc(peers));
}

// ---------------------------------------------------------------------------
// Monolithic: 1 CTA per row. Stream read + zero-fill + smem candidate gather,
// then inline ~500-cycle rank-select + scatter. No global scratch at all.
// ---------------------------------------------------------------------------
__global__ __launch_bounds__(NTH) void topk_kernel(
    const float* __restrict__ x, float* __restrict__ out)
{
    __shared__ __align__(16) unsigned long long s_keys[CAND_CAP + 2];
    __shared__ int s_cnt;
    __shared__ int s_hist[256];
    __shared__ int s_digit, s_want, s_bcnt;

    const int row = blockIdx.x;
    const size_t row_off = (size_t)row * COLS;
    const int tid = threadIdx.x;

    if (tid == 0) s_cnt = 0;
    __syncthreads();

    const float4* __restrict__ xin = reinterpret_cast<const float4*>(x + row_off);
    float4* __restrict__       zo  = reinterpret_cast<float4*>(out + row_off);
    const float4 z4 = make_float4(0.f, 0.f, 0.f, 0.f);

    // ---------------- Phase 1: stream (4 groups of 4 front-batched float4) --
    #pragma unroll
    for (int g = 0; g < GROUPS; g++) {
        float4 v[BATCH];
        #pragma unroll
        for (int k = 0; k < BATCH; k++)
            v[k] = __ldcs(&xin[tid + (g * BATCH + k) * NTH]);
        #pragma unroll
        for (int k = 0; k < BATCH; k++)
            __stcs(&zo[tid + (g * BATCH + k) * NTH], z4);
        #pragma unroll
        for (int k = 0; k < BATCH; k++) {
            const int gidx = (tid + (g * BATCH + k) * NTH) * 4;
            if (v[k].x >= PRE_THRESH) { int p = atomicAdd(&s_cnt, 1); if (p < CAND_CAP) s_keys[p] = make_key(v[k].x, gidx + 0); }
            if (v[k].y >= PRE_THRESH) { int p = atomicAdd(&s_cnt, 1); if (p < CAND_CAP) s_keys[p] = make_key(v[k].y, gidx + 1); }
            if (v[k].z >= PRE_THRESH) { int p = atomicAdd(&s_cnt, 1); if (p < CAND_CAP) s_keys[p] = make_key(v[k].z, gidx + 2); }
            if (v[k].w >= PRE_THRESH) { int p = atomicAdd(&s_cnt, 1); if (p < CAND_CAP) s_keys[p] = make_key(v[k].w, gidx + 3); }
        }
    }
    __syncthreads();

    const int cnt = s_cnt;
    // zero-pad the odd slot so the LDS.128 pair loop is exact (0 < any key)
    if (tid == 0 && (cnt & 1) && cnt < CAND_CAP) s_keys[cnt] = 0;
    __syncthreads();

    const bool fast = (cnt >= K_TOP) && (cnt <= CAND_CAP);

    if (fast) {
        // ------------- Phase 2: rank-select over unique keys (inline) ------
        if (tid < cnt) {
            const unsigned long long k0 = s_keys[tid];
            const ulonglong2* __restrict__ kv =
                reinterpret_cast<const ulonglong2*>(s_keys);
            const int nh = (cnt + 1) >> 1;
            int r0 = 0;
            #pragma unroll 4
            for (int j = 0; j < nh; j++) {
                const ulonglong2 p = kv[j];          // LDS.128 broadcast
                r0 += (int)(p.x > k0) + (int)(p.y > k0);
            }
            if (r0 < K_TOP) {
                const int idx = (int)(~(unsigned)k0) & (COLS - 1);
                out[row_off + idx] = fmaxf(unfmap((unsigned)(k0 >> 32)), 0.f);
            }
        }
    } else {
        // ------------- Fallback: in-block full-row radix (exact) -----------
        unsigned long long prefix = 0, T = 0;
        int want = K_TOP;
        for (int shift = 56; shift >= 0; shift -= 8) {
            if (tid < 256) s_hist[tid] = 0;
            __syncthreads();
            for (int j = tid; j < COLS; j += NTH) {
                unsigned long long key = make_key(x[row_off + j], j);
                if (shift == 56 || (key >> (shift + 8)) == prefix)
                    hist_add(s_hist, (int)((key >> shift) & 255));
            }
            __syncthreads();
            if (tid == 0) {
                int acc = 0, d = 255;
                for (; d >= 0; d--) {
                    if (acc + s_hist[d] >= want) break;
                    acc += s_hist[d];
                }
                if (d < 0) d = 0;
                s_digit = d; s_want = want - acc; s_bcnt = s_hist[d];
            }
            __syncthreads();
            prefix = (prefix << 8) | (unsigned long long)s_digit;
            want   = s_want;
            const int c = s_bcnt;
            if (want == c) { T = prefix << shift; break; }
            __syncthreads();
            // unique keys -> at shift==0, c==1==want, so the break always fires
        }
        for (int j = tid; j < COLS; j += NTH) {
            unsigned long long key = make_key(x[row_off + j], j);
            if (key >= T) {
                const int idx = (int)(~(unsigned)key) & (COLS - 1);
                out[row_off + idx] = fmaxf(unfmap((unsigned)(key >> 32)), 0.f);
            }
        }
    }
}

extern "C" void kernel_launch(void* const* d_in, const int* in_sizes, int n_in,
                              void* d_out, int out_size)
{
    const float* x = (const float*)d_in[0];
    float* out = (float*)d_out;
    topk_kernel<<<ROWS, NTH>>>(x, out);
}

// round 12
// speedup vs baseline: 1.1258x; 1.0313x over previous
#include <cuda_runtime.h>
#include <cstdint>

#define ROWS        8192
#define COLS        32768
#define K_TOP       32
#define PRE_THRESH  2.8f

#define NTH         512
#define VEC         8                       // floats per access (256-bit)
#define ITERS       (COLS / VEC / NTH)      // 8 v8-accesses per thread
#define BATCH       2                       // front-batched v8 loads per group
#define GROUPS      (ITERS / BATCH)         // 4
#define CAND_CAP    192                     // mean ~84, sigma ~9.1 -> 11.8 sigma

__device__ __forceinline__ unsigned fmap(float f) {
    unsigned b = __float_as_uint(f);
    return (b & 0x80000000u) ? ~b : (b | 0x80000000u);
}
__device__ __forceinline__ float unfmap(unsigned u) {
    unsigned b = (u & 0x80000000u) ? (u ^ 0x80000000u) : ~u;
    return __uint_as_float(b);
}
// unique key: value desc, index asc tiebreak (matches jax.lax.top_k)
__device__ __forceinline__ unsigned long long make_key(float v, int idx) {
    return ((unsigned long long)fmap(v) << 32) | (unsigned)(~idx);
}

// 256-bit streaming global load/store (sm_100+)
__device__ __forceinline__ void ldg8_cs(const float* p, float* v) {
    asm volatile("ld.global.cs.v8.f32 {%0,%1,%2,%3,%4,%5,%6,%7}, [%8];"
                 : "=f"(v[0]), "=f"(v[1]), "=f"(v[2]), "=f"(v[3]),
                   "=f"(v[4]), "=f"(v[5]), "=f"(v[6]), "=f"(v[7])
                 : "l"(p));
}
__device__ __forceinline__ void stg8_cs_zero(float* p) {
    asm volatile("st.global.cs.v8.f32 [%0], {%1,%1,%1,%1,%1,%1,%1,%1};"
                 :: "l"(p), "f"(0.0f) : "memory");
}

// warp-aggregated histogram add (fallback path only)
__device__ __forceinline__ void hist_add(int* hist, int digit) {
    const unsigned act   = __activemask();
    const unsigned peers = __match_any_sync(act, digit);
    const int      lane  = threadIdx.x & 31;
    if ((__ffs(peers) - 1) == lane)
        atomicAdd(&hist[digit], __popc(peers));
}

// ---------------------------------------------------------------------------
// Monolithic: 1 CTA per row. 256-bit stream read + zero-fill + smem candidate
// gather, then inline ~500-cycle rank-select + scatter. No global scratch.
// ---------------------------------------------------------------------------
__global__ __launch_bounds__(NTH) void topk_kernel(
    const float* __restrict__ x, float* __restrict__ out)
{
    __shared__ __align__(16) unsigned long long s_keys[CAND_CAP + 2];
    __shared__ int s_cnt;
    __shared__ int s_hist[256];
    __shared__ int s_digit, s_want, s_bcnt;

    const int row = blockIdx.x;
    const size_t row_off = (size_t)row * COLS;
    const int tid = threadIdx.x;

    if (tid == 0) s_cnt = 0;
    __syncthreads();

    const float* __restrict__ xin = x + row_off;
    float* __restrict__       zo  = out + row_off;

    // ------------- Phase 1: stream (groups of BATCH front-batched v8) ------
    #pragma unroll
    for (int g = 0; g < GROUPS; g++) {
        float v[BATCH][VEC];
        #pragma unroll
        for (int k = 0; k < BATCH; k++)
            ldg8_cs(xin + (tid + (g * BATCH + k) * NTH) * VEC, v[k]);
        #pragma unroll
        for (int k = 0; k < BATCH; k++)
            stg8_cs_zero(zo + (tid + (g * BATCH + k) * NTH) * VEC);
        #pragma unroll
        for (int k = 0; k < BATCH; k++) {
            const int gidx = (tid + (g * BATCH + k) * NTH) * VEC;
            #pragma unroll
            for (int e = 0; e < VEC; e++) {
                if (v[k][e] >= PRE_THRESH) {
                    int p = atomicAdd(&s_cnt, 1);
                    if (p < CAND_CAP) s_keys[p] = make_key(v[k][e], gidx + e);
                }
            }
        }
    }
    __syncthreads();

    const int cnt = s_cnt;
    // zero-pad the odd slot so the LDS.128 pair loop is exact (0 < any key)
    if (tid == 0 && (cnt & 1) && cnt < CAND_CAP) s_keys[cnt] = 0;
    __syncthreads();

    const bool fast = (cnt >= K_TOP) && (cnt <= CAND_CAP);

    if (fast) {
        // ------------- Phase 2: rank-select over unique keys (inline) ------
        if (tid < cnt) {
            const unsigned long long k0 = s_keys[tid];
            const ulonglong2* __restrict__ kv =
                reinterpret_cast<const ulonglong2*>(s_keys);
            const int nh = (cnt + 1) >> 1;
            int r0 = 0;
            #pragma unroll 4
            for (int j = 0; j < nh; j++) {
                const ulonglong2 p = kv[j];          // LDS.128 broadcast
                r0 += (int)(p.x > k0) + (int)(p.y > k0);
            }
            if (r0 < K_TOP) {
                const int idx = (int)(~(unsigned)k0) & (COLS - 1);
                out[row_off + idx] = fmaxf(unfmap((unsigned)(k0 >> 32)), 0.f);
            }
        }
    } else {
        // ------------- Fallback: in-block full-row radix (exact) -----------
        unsigned long long prefix = 0, T = 0;
        int want = K_TOP;
        for (int shift = 56; shift >= 0; shift -= 8) {
            if (tid < 256) s_hist[tid] = 0;
            __syncthreads();
            for (int j = tid; j < COLS; j += NTH) {
                unsigned long long key = make_key(x[row_off + j], j);
                if (shift == 56 || (key >> (shift + 8)) == prefix)
                    hist_add(s_hist, (int)((key >> shift) & 255));
            }
            __syncthreads();
            if (tid == 0) {
                int acc = 0, d = 255;
                for (; d >= 0; d--) {
                    if (acc + s_hist[d] >= want) break;
                    acc += s_hist[d];
                }
                if (d < 0) d = 0;
                s_digit = d; s_want = want - acc; s_bcnt = s_hist[d];
            }
            __syncthreads();
            prefix = (prefix << 8) | (unsigned long long)s_digit;
            want   = s_want;
            const int c = s_bcnt;
            if (want == c) { T = prefix << shift; break; }
            __syncthreads();
            // unique keys -> at shift==0, c==1==want, so the break always fires
        }
        for (int j = tid; j < COLS; j += NTH) {
            unsigned long long key = make_key(x[row_off + j], j);
            if (key >= T) {
                const int idx = (int)(~(unsigned)key) & (COLS - 1);
                out[row_off + idx] = fmaxf(unfmap((unsigned)(key >> 32)), 0.f);
            }
        }
    }
}

extern "C" void kernel_launch(void* const* d_in, const int* in_sizes, int n_in,
                              void* d_out, int out_size)
{
    const float* x = (const float*)d_in[0];
    float* out = (float*)d_out;
    topk_kernel<<<ROWS, NTH>>>(x, out);
}

// round 13
// speedup vs baseline: 1.1280x; 1.0019x over previous
#include <cuda_runtime.h>
#include <cstdint>

#define ROWS        8192
#define COLS        32768
#define K_TOP       32
#define PRE_THRESH  2.8f

#define NTH         512
#define VEC         8                       // floats per access (256-bit)
#define ITERS       (COLS / VEC / NTH)      // 8 v8-accesses per thread
#define BATCH       2                       // v8 loads per group
#define GROUPS      (ITERS / BATCH)         // 4
#define CAND_CAP    192                     // mean ~84, sigma ~9.1 -> 11.8 sigma

__device__ __forceinline__ unsigned fmap(float f) {
    unsigned b = __float_as_uint(f);
    return (b & 0x80000000u) ? ~b : (b | 0x80000000u);
}
__device__ __forceinline__ float unfmap(unsigned u) {
    unsigned b = (u & 0x80000000u) ? (u ^ 0x80000000u) : ~u;
    return __uint_as_float(b);
}
// unique key: value desc, index asc tiebreak (matches jax.lax.top_k)
__device__ __forceinline__ unsigned long long make_key(float v, int idx) {
    return ((unsigned long long)fmap(v) << 32) | (unsigned)(~idx);
}

// 256-bit streaming global load/store (sm_100+)
__device__ __forceinline__ void ldg8_cs(const float* p, float* v) {
    asm volatile("ld.global.cs.v8.f32 {%0,%1,%2,%3,%4,%5,%6,%7}, [%8];"
                 : "=f"(v[0]), "=f"(v[1]), "=f"(v[2]), "=f"(v[3]),
                   "=f"(v[4]), "=f"(v[5]), "=f"(v[6]), "=f"(v[7])
                 : "l"(p));
}
__device__ __forceinline__ void stg8_cs_zero(float* p) {
    asm volatile("st.global.cs.v8.f32 [%0], {%1,%1,%1,%1,%1,%1,%1,%1};"
                 :: "l"(p), "f"(0.0f) : "memory");
}

// warp-aggregated histogram add (fallback path only)
__device__ __forceinline__ void hist_add(int* hist, int digit) {
    const unsigned act   = __activemask();
    const unsigned peers = __match_any_sync(act, digit);
    const int      lane  = threadIdx.x & 31;
    if ((__ffs(peers) - 1) == lane)
        atomicAdd(&hist[digit], __popc(peers));
}

// ---------------------------------------------------------------------------
// Monolithic: 1 CTA per row. Software-pipelined 256-bit stream (loads for
// group g+1 in flight while group g is stored/processed), smem candidate
// gather, inline rank-select + scatter. No global scratch.
// ---------------------------------------------------------------------------
__global__ __launch_bounds__(NTH) void topk_kernel(
    const float* __restrict__ x, float* __restrict__ out)
{
    __shared__ __align__(16) unsigned long long s_keys[CAND_CAP + 2];
    __shared__ int s_cnt;
    __shared__ int s_hist[256];
    __shared__ int s_digit, s_want, s_bcnt;

    const int row = blockIdx.x;
    const size_t row_off = (size_t)row * COLS;
    const int tid = threadIdx.x;

    if (tid == 0) s_cnt = 0;
    __syncthreads();

    const float* __restrict__ xin = x + row_off;
    float* __restrict__       zo  = out + row_off;

    // ------------- Phase 1: software-pipelined stream ----------------------
    float v[2][BATCH][VEC];

    // prologue: group 0 loads
    #pragma unroll
    for (int k = 0; k < BATCH; k++)
        ldg8_cs(xin + (tid + k * NTH) * VEC, v[0][k]);

    #pragma unroll
    for (int g = 0; g < GROUPS; g++) {
        const int cur = g & 1;
        // issue next group's loads first: keep them in flight during process
        if (g + 1 < GROUPS) {
            #pragma unroll
            for (int k = 0; k < BATCH; k++)
                ldg8_cs(xin + (tid + ((g + 1) * BATCH + k) * NTH) * VEC,
                        v[(g + 1) & 1][k]);
        }
        // store zeros for current group
        #pragma unroll
        for (int k = 0; k < BATCH; k++)
            stg8_cs_zero(zo + (tid + (g * BATCH + k) * NTH) * VEC);
        // process current group's candidates
        #pragma unroll
        for (int k = 0; k < BATCH; k++) {
            const int gidx = (tid + (g * BATCH + k) * NTH) * VEC;
            #pragma unroll
            for (int e = 0; e < VEC; e++) {
                if (v[cur][k][e] >= PRE_THRESH) {
                    int p = atomicAdd(&s_cnt, 1);
                    if (p < CAND_CAP) s_keys[p] = make_key(v[cur][k][e], gidx + e);
                }
            }
        }
    }
    __syncthreads();

    const int cnt = s_cnt;
    // zero-pad the odd slot so the LDS.128 pair loop is exact (0 < any key)
    if (tid == 0 && (cnt & 1) && cnt < CAND_CAP) s_keys[cnt] = 0;
    __syncthreads();

    const bool fast = (cnt >= K_TOP) && (cnt <= CAND_CAP);

    if (fast) {
        // ------------- Phase 2: rank-select over unique keys (inline) ------
        if (tid < cnt) {
            const unsigned long long k0 = s_keys[tid];
            const ulonglong2* __restrict__ kv =
                reinterpret_cast<const ulonglong2*>(s_keys);
            const int nh = (cnt + 1) >> 1;
            int r0 = 0;
            #pragma unroll 4
            for (int j = 0; j < nh; j++) {
                const ulonglong2 p = kv[j];          // LDS.128 broadcast
                r0 += (int)(p.x > k0) + (int)(p.y > k0);
            }
            if (r0 < K_TOP) {
                const int idx = (int)(~(unsigned)k0) & (COLS - 1);
                out[row_off + idx] = fmaxf(unfmap((unsigned)(k0 >> 32)), 0.f);
            }
        }
    } else {
        // ------------- Fallback: in-block full-row radix (exact) -----------
        unsigned long long prefix = 0, T = 0;
        int want = K_TOP;
        for (int shift = 56; shift >= 0; shift -= 8) {
            if (tid < 256) s_hist[tid] = 0;
            __syncthreads();
            for (int j = tid; j < COLS; j += NTH) {
                unsigned long long key = make_key(x[row_off + j], j);
                if (shift == 56 || (key >> (shift + 8)) == prefix)
                    hist_add(s_hist, (int)((key >> shift) & 255));
            }
            __syncthreads();
            if (tid == 0) {
                int acc = 0, d = 255;
                for (; d >= 0; d--) {
                    if (acc + s_hist[d] >= want) break;
                    acc += s_hist[d];
                }
                if (d < 0) d = 0;
                s_digit = d; s_want = want - acc; s_bcnt = s_hist[d];
            }
            __syncthreads();
            prefix = (prefix << 8) | (unsigned long long)s_digit;
            want   = s_want;
            const int c = s_bcnt;
            if (want == c) { T = prefix << shift; break; }
            __syncthreads();
            // unique keys -> at shift==0, c==1==want, so the break always fires
        }
        for (int j = tid; j < COLS; j += NTH) {
            unsigned long long key = make_key(x[row_off + j], j);
            if (key >= T) {
                const int idx = (int)(~(unsigned)key) & (COLS - 1);
                out[row_off + idx] = fmaxf(unfmap((unsigned)(key >> 32)), 0.f);
            }
        }
    }
}

extern "C" void kernel_launch(void* const* d_in, const int* in_sizes, int n_in,
                              void* d_out, int out_size)
{
    const float* x = (const float*)d_in[0];
    float* out = (float*)d_out;
    topk_kernel<<<ROWS, NTH>>>(x, out);
}